// round 6
// baseline (speedup 1.0000x reference)
#include <cuda_runtime.h>
#include <cuda_bf16.h>
#include <cstdint>

// ---------------- problem constants ----------------
#define T_TOT 16
#define KLAG  4
#define TT    12          // T - K
#define BB    32
#define CC    256
#define HWN   256
#define ELEMS_T (BB*CC*HWN)       // 2097152 elements per timestep
#define VEC_T   (ELEMS_T/4)       // 524288 float4 per timestep

#define OUT_LOSS_OFF  33554432ull
#define OUT_LSP_OFF   33554433ull
#define OUT_LSN_OFF   33554817ull // 33554433 + 384

// ---------------- scratch (no allocs allowed) ----------------
__device__ signed char g_ctx[(size_t)TT * ELEMS_T];   // context bits, t = 0..11  (25 MB)
__device__ signed char g_spk[(size_t)TT * ELEMS_T];   // spk bits, slot t holds real t+4
__device__ float g_pos[TT * BB];
__device__ float g_neg[TT * BB];                      // keyed by spk batch
__device__ int   g_inv[BB];

// ---------------- helpers ----------------
__device__ __forceinline__ uint32_t smem_u32(const void* p) {
    uint32_t a;
    asm("{ .reg .u64 t; cvta.to.shared.u64 t, %1; cvt.u32.u64 %0, t; }"
        : "=r"(a) : "l"(p));
    return a;
}

__device__ __forceinline__ void ldm_x4(uint32_t addr, uint32_t* d) {
    asm volatile("ldmatrix.sync.aligned.m8n8.x4.shared.b16 {%0,%1,%2,%3}, [%4];"
        : "=r"(d[0]), "=r"(d[1]), "=r"(d[2]), "=r"(d[3]) : "r"(addr));
}
__device__ __forceinline__ void ldm_x2(uint32_t addr, uint32_t& b0, uint32_t& b1) {
    asm volatile("ldmatrix.sync.aligned.m8n8.x2.shared.b16 {%0,%1}, [%2];"
        : "=r"(b0), "=r"(b1) : "r"(addr));
}
__device__ __forceinline__ void imma(int* c, const uint32_t* a, uint32_t b0, uint32_t b1) {
    asm volatile("mma.sync.aligned.m16n8k32.row.col.s32.s8.s8.s32 "
        "{%0,%1,%2,%3}, {%4,%5,%6,%7}, {%8,%9}, {%0,%1,%2,%3};"
        : "+r"(c[0]), "+r"(c[1]), "+r"(c[2]), "+r"(c[3])
        : "r"(a[0]), "r"(a[1]), "r"(a[2]), "r"(a[3]), "r"(b0), "r"(b1));
}

// magic int->float for small non-negative ints (avoids I2F)
__device__ __forceinline__ float i2f_small(int v) {
    return __uint_as_float((uint32_t)v | 0x4B000000u) - 8388608.0f;
}

// ---------------- kernel 1: inverse permutation ----------------
__global__ void prep_kernel(const int* __restrict__ ridx) {
    int i = threadIdx.x;
    if (i < BB) g_inv[ridx[i]] = i;
}

// ---------------- kernel 2: copy + exact fp32 scan -> int8 scratch ----------------
__global__ void __launch_bounds__(256)
scan_copy_kernel(const float4* __restrict__ in, float4* __restrict__ out) {
    int i = blockIdx.x * 256 + threadIdx.x;          // 0..524287, 4 hw-elements each
    float4 m = make_float4(0.f, 0.f, 0.f, 0.f);
    uint32_t* ctxp = reinterpret_cast<uint32_t*>(g_ctx);
    uint32_t* spkp = reinterpret_cast<uint32_t*>(g_spk);
#pragma unroll
    for (int t = 0; t < T_TOT; ++t) {
        float4 v = in[(size_t)t * VEC_T + i];
        out[(size_t)t * VEC_T + i] = v;
        // reset from carried mem, then update, then spike (all dyadic -> exact fp32)
        float rx = m.x > 1.0f ? 1.0f : 0.0f;
        float ry = m.y > 1.0f ? 1.0f : 0.0f;
        float rz = m.z > 1.0f ? 1.0f : 0.0f;
        float rw = m.w > 1.0f ? 1.0f : 0.0f;
        m.x = 0.5f * m.x + v.x - rx;
        m.y = 0.5f * m.y + v.y - ry;
        m.z = 0.5f * m.z + v.z - rz;
        m.w = 0.5f * m.w + v.w - rw;
        if (t < TT) {
            uint32_t u = (m.x > 1.0f ? 1u : 0u)
                       | (m.y > 1.0f ? 0x100u : 0u)
                       | (m.z > 1.0f ? 0x10000u : 0u)
                       | (m.w > 1.0f ? 0x1000000u : 0u);
            ctxp[(size_t)t * VEC_T + i] = u;
        }
        if (t >= KLAG) {
            uint32_t u = (v.x != 0.f ? 1u : 0u)
                       | (v.y != 0.f ? 0x100u : 0u)
                       | (v.z != 0.f ? 0x10000u : 0u)
                       | (v.w != 0.f ? 0x1000000u : 0u);
            spkp[(size_t)(t - KLAG) * VEC_T + i] = u;
        }
    }
}

// ---------------- kernel 3: Gram via s8 IMMA + fused W contraction ----------------
// Per CTA (t, b): A_pos = ctx[t,b] @ spk[t+4,b]^T ; A_neg = ctx[t,inv[b]] @ spk[t+4,b]^T
// score contribution = sum_{c,c'} W[c,c'] * A[c,c'].  One warp owns 32 ctx rows.

#define PITCH   272                       // 256 + 16 pad -> conflict-free ldmatrix
#define SPK_OFF 0
#define CTX_OFF (256 * PITCH)             // 69632
#define DSMEM   (2 * 256 * PITCH)         // 139264

__device__ __forceinline__ float gram_w(uint32_t smc, uint32_t sms,
                                        const float* __restrict__ Wmat,
                                        int warp, int lane) {
    // A fragments: rows warp*32 .. warp*32+31, full K=256 (held in regs)
    uint32_t a[2][8][4];
    int sel = lane >> 3;
    int r7  = lane & 7;
    int aoff = ((sel & 1) * 8 + r7) * PITCH + (sel >> 1) * 16;
#pragma unroll
    for (int rb = 0; rb < 2; ++rb) {
#pragma unroll
        for (int ks = 0; ks < 8; ++ks) {
            ldm_x4(smc + (uint32_t)((warp * 32 + rb * 16) * PITCH + ks * 32) + aoff,
                   a[rb][ks]);
        }
    }
    int tg = lane >> 2, t4 = lane & 3;
    uint32_t bbase = sms + (uint32_t)(r7 * PITCH + ((lane >> 3) & 1) * 16);
    float sum = 0.f;
#pragma unroll 2
    for (int nb = 0; nb < 32; ++nb) {
        int acc[8] = {0, 0, 0, 0, 0, 0, 0, 0};
#pragma unroll
        for (int ks = 0; ks < 8; ++ks) {
            uint32_t b0, b1;
            ldm_x2(bbase + (uint32_t)(nb * 8 * PITCH + ks * 32), b0, b1);
            imma(acc,     a[0][ks], b0, b1);
            imma(acc + 4, a[1][ks], b0, b1);
        }
        int cp = nb * 8 + 2 * t4;
        const float* Wp = Wmat + (size_t)(warp * 32 + tg) * 256 + cp;
#pragma unroll
        for (int rb = 0; rb < 2; ++rb) {
            float2 wa = __ldg((const float2*)(Wp + (size_t)(rb * 16) * 256));
            float2 wb = __ldg((const float2*)(Wp + (size_t)(rb * 16 + 8) * 256));
            sum += i2f_small(acc[rb * 4 + 0]) * wa.x
                 + i2f_small(acc[rb * 4 + 1]) * wa.y
                 + i2f_small(acc[rb * 4 + 2]) * wb.x
                 + i2f_small(acc[rb * 4 + 3]) * wb.y;
        }
    }
    return sum;
}

__global__ void __launch_bounds__(256, 1)
gemm_score_kernel(const float* __restrict__ Wmat) {
    extern __shared__ __align__(16) char dsm[];
    __shared__ float s_red[16];
    int tid = threadIdx.x, warp = tid >> 5, lane = tid & 31;
    int t = blockIdx.x >> 5, b = blockIdx.x & 31;

    const uint4* spk4 = (const uint4*)g_spk + (size_t)(t * BB + b) * 4096;
    const uint4* ctx4 = (const uint4*)g_ctx;
    const uint4* cpos = ctx4 + (size_t)(t * BB + b) * 4096;
    for (int id = tid; id < 4096; id += 256) {
        int row = id >> 4, q = id & 15;
        *(uint4*)(dsm + SPK_OFF + row * PITCH + q * 16) = spk4[id];
        *(uint4*)(dsm + CTX_OFF + row * PITCH + q * 16) = cpos[id];
    }
    int binv = g_inv[b];
    __syncthreads();

    uint32_t smc = smem_u32(dsm + CTX_OFF);
    uint32_t sms = smem_u32(dsm + SPK_OFF);

    float sumPos = gram_w(smc, sms, Wmat, warp, lane);
    __syncthreads();

    const uint4* cneg = ctx4 + (size_t)(t * BB + binv) * 4096;
    for (int id = tid; id < 4096; id += 256) {
        int row = id >> 4, q = id & 15;
        *(uint4*)(dsm + CTX_OFF + row * PITCH + q * 16) = cneg[id];
    }
    __syncthreads();

    float sumNeg = gram_w(smc, sms, Wmat, warp, lane);

#pragma unroll
    for (int o = 16; o; o >>= 1) {
        sumPos += __shfl_xor_sync(0xffffffffu, sumPos, o);
        sumNeg += __shfl_xor_sync(0xffffffffu, sumNeg, o);
    }
    if (lane == 0) { s_red[warp] = sumPos; s_red[8 + warp] = sumNeg; }
    __syncthreads();
    if (tid == 0) {
        float p = 0.f, n = 0.f;
#pragma unroll
        for (int w = 0; w < 8; ++w) { p += s_red[w]; n += s_red[8 + w]; }
        g_pos[t * BB + b] = p;
        g_neg[t * BB + b] = n;
    }
}

// ---------------- kernel 4: finalize scores + loss ----------------
__global__ void __launch_bounds__(384)
finalize_kernel(float* __restrict__ out) {
    __shared__ float s_red[TT * BB];
    __shared__ float s_lsn[TT];
    int i = threadIdx.x;            // 0..383 = t*32 + b
    int t = i >> 5;
    float mp = g_pos[i] * (1.0f / 65536.0f);
    float mn = g_neg[i] * (1.0f / 65536.0f);
    float lsp = logf(expf(mp) + 1e-4f);
    float sn = expf(mn) + 1e-4f;
    float s = sn;
#pragma unroll
    for (int o = 16; o; o >>= 1) s += __shfl_xor_sync(0xffffffffu, s, o);
    float lsn = logf(s);            // permutation-invariant sum over batch
    out[OUT_LSP_OFF + i] = lsp;
    if ((i & 31) == 0) s_lsn[t] = lsn;
    s_red[i] = lsn - lsp;
    __syncthreads();
    if (i < TT) out[OUT_LSN_OFF + i] = s_lsn[i];
    if (i == 0) {
        float acc = 0.f;
        for (int j = 0; j < TT * BB; ++j) acc += s_red[j];
        out[OUT_LOSS_OFF] = acc * (1.0f / (TT * BB));
    }
}

// ---------------- launch ----------------
extern "C" void kernel_launch(void* const* d_in, const int* in_sizes, int n_in,
                              void* d_out, int out_size) {
    const float* spk = (const float*)d_in[0];
    // d_in[1] = mem_rec (unused by reference outputs)
    const float* W = (const float*)d_in[2];
    const int* ridx = (const int*)d_in[3];
    float* out = (float*)d_out;

    cudaFuncSetAttribute(gemm_score_kernel,
                         cudaFuncAttributeMaxDynamicSharedMemorySize, DSMEM);

    prep_kernel<<<1, 32>>>(ridx);
    scan_copy_kernel<<<VEC_T / 256, 256>>>((const float4*)spk, (float4*)out);
    gemm_score_kernel<<<TT * BB, 256, DSMEM>>>(W);
    finalize_kernel<<<1, TT * BB>>>(out);
}

// round 10
// speedup vs baseline: 1.0877x; 1.0877x over previous
#include <cuda_runtime.h>
#include <cuda_bf16.h>
#include <cstdint>

// ---------------- problem constants ----------------
#define T_TOT 16
#define KLAG  4
#define TT    12          // T - K
#define BB    32
#define CC    256
#define HWN   256
#define ELEMS_T (BB*CC*HWN)       // 2097152 elements per timestep
#define VEC_T   (ELEMS_T/4)       // 524288 float4 per timestep

#define OUT_LOSS_OFF  33554432ull
#define OUT_LSP_OFF   33554433ull
#define OUT_LSN_OFF   33554817ull // 33554433 + 384

// ---------------- scratch (no allocs allowed) ----------------
__device__ signed char g_ctx[(size_t)TT * ELEMS_T];   // context bits, t = 0..11  (25 MB)
__device__ signed char g_spk[(size_t)TT * ELEMS_T];   // spk bits, slot t holds real t+4
__device__ float g_pos[TT * BB];
__device__ float g_neg[TT * BB];                      // keyed by spk batch
__device__ int   g_inv[BB];

// ---------------- helpers ----------------
__device__ __forceinline__ uint32_t smem_u32(const void* p) {
    uint32_t a;
    asm("{ .reg .u64 t; cvta.to.shared.u64 t, %1; cvt.u32.u64 %0, t; }"
        : "=r"(a) : "l"(p));
    return a;
}

__device__ __forceinline__ void ldm_x4(uint32_t addr, uint32_t* d) {
    asm volatile("ldmatrix.sync.aligned.m8n8.x4.shared.b16 {%0,%1,%2,%3}, [%4];"
        : "=r"(d[0]), "=r"(d[1]), "=r"(d[2]), "=r"(d[3]) : "r"(addr));
}
__device__ __forceinline__ void ldm_x2(uint32_t addr, uint32_t& b0, uint32_t& b1) {
    asm volatile("ldmatrix.sync.aligned.m8n8.x2.shared.b16 {%0,%1}, [%2];"
        : "=r"(b0), "=r"(b1) : "r"(addr));
}
__device__ __forceinline__ void imma(int* c, const uint32_t* a, uint32_t b0, uint32_t b1) {
    asm volatile("mma.sync.aligned.m16n8k32.row.col.s32.s8.s8.s32 "
        "{%0,%1,%2,%3}, {%4,%5,%6,%7}, {%8,%9}, {%0,%1,%2,%3};"
        : "+r"(c[0]), "+r"(c[1]), "+r"(c[2]), "+r"(c[3])
        : "r"(a[0]), "r"(a[1]), "r"(a[2]), "r"(a[3]), "r"(b0), "r"(b1));
}

// magic int->float for small non-negative ints (avoids I2F)
__device__ __forceinline__ float i2f_small(int v) {
    return __uint_as_float((uint32_t)v | 0x4B000000u) - 8388608.0f;
}

// ---------------- kernel 1: inverse permutation ----------------
__global__ void prep_kernel(const int* __restrict__ ridx) {
    int i = threadIdx.x;
    if (i < BB) g_inv[ridx[i]] = i;
}

// ---------------- kernel 2: copy + exact fp32 scan -> int8 scratch ----------------
__global__ void __launch_bounds__(256)
scan_copy_kernel(const float4* __restrict__ in, float4* __restrict__ out) {
    int i = blockIdx.x * 256 + threadIdx.x;          // 0..524287, 4 hw-elements each
    float4 m = make_float4(0.f, 0.f, 0.f, 0.f);
    uint32_t* ctxp = reinterpret_cast<uint32_t*>(g_ctx);
    uint32_t* spkp = reinterpret_cast<uint32_t*>(g_spk);
#pragma unroll
    for (int t = 0; t < T_TOT; ++t) {
        float4 v = in[(size_t)t * VEC_T + i];
        out[(size_t)t * VEC_T + i] = v;
        // reset from carried mem, then update, then spike (all dyadic -> exact fp32)
        float rx = m.x > 1.0f ? 1.0f : 0.0f;
        float ry = m.y > 1.0f ? 1.0f : 0.0f;
        float rz = m.z > 1.0f ? 1.0f : 0.0f;
        float rw = m.w > 1.0f ? 1.0f : 0.0f;
        m.x = 0.5f * m.x + v.x - rx;
        m.y = 0.5f * m.y + v.y - ry;
        m.z = 0.5f * m.z + v.z - rz;
        m.w = 0.5f * m.w + v.w - rw;
        if (t < TT) {
            uint32_t u = (m.x > 1.0f ? 1u : 0u)
                       | (m.y > 1.0f ? 0x100u : 0u)
                       | (m.z > 1.0f ? 0x10000u : 0u)
                       | (m.w > 1.0f ? 0x1000000u : 0u);
            ctxp[(size_t)t * VEC_T + i] = u;
        }
        if (t >= KLAG) {
            uint32_t u = (v.x != 0.f ? 1u : 0u)
                       | (v.y != 0.f ? 0x100u : 0u)
                       | (v.z != 0.f ? 0x10000u : 0u)
                       | (v.w != 0.f ? 0x1000000u : 0u);
            spkp[(size_t)(t - KLAG) * VEC_T + i] = u;
        }
    }
}

// ---------------- kernel 3: fused pos+neg Gram via s8 IMMA + single-W contraction ----
// Per CTA (t, b):
//   A_pos = ctx[t,b]      @ spk[t+4,b]^T
//   A_neg = ctx[t,inv[b]] @ spk[t+4,b]^T        (valid: batch-sum of neg scores is
//                                                permutation-invariant)
//   s_pos/s_neg = sum_{c,c'} W[c,c'] * A[c,c']  (W loaded ONCE, used for both)
// 512 threads = 16 warps; warp w owns ctx rows [16w, 16w+16).

#define PITCH    272                       // 256 + 16 pad -> conflict-free ldmatrix
#define SPK_OFF  0
#define CTXP_OFF (256 * PITCH)             // 69632
#define CTXN_OFF (2 * 256 * PITCH)         // 139264
#define DSMEM    (3 * 256 * PITCH)         // 208896

__global__ void __launch_bounds__(512, 1)
gemm_score_kernel(const float* __restrict__ Wmat) {
    extern __shared__ __align__(16) char dsm[];
    __shared__ float s_red[32];
    int tid = threadIdx.x, warp = tid >> 5, lane = tid & 31;
    int t = blockIdx.x >> 5, b = blockIdx.x & 31;

    int binv = g_inv[b];
    const uint4* spk4 = (const uint4*)g_spk + (size_t)(t * BB + b) * 4096;
    const uint4* cpos = (const uint4*)g_ctx + (size_t)(t * BB + b) * 4096;
    const uint4* cneg = (const uint4*)g_ctx + (size_t)(t * BB + binv) * 4096;
    for (int id = tid; id < 4096; id += 512) {
        int row = id >> 4, q = id & 15;
        int off = row * PITCH + q * 16;
        *(uint4*)(dsm + SPK_OFF + off)  = spk4[id];
        *(uint4*)(dsm + CTXP_OFF + off) = cpos[id];
        *(uint4*)(dsm + CTXN_OFF + off) = cneg[id];
    }
    __syncthreads();

    uint32_t smp = smem_u32(dsm + CTXP_OFF);
    uint32_t smn = smem_u32(dsm + CTXN_OFF);
    uint32_t sms = smem_u32(dsm + SPK_OFF);

    // A fragments for this warp's 16 rows, full K=256, pos and neg ctx
    int sel = lane >> 3;
    int r7  = lane & 7;
    int aoff = ((sel & 1) * 8 + r7) * PITCH + (sel >> 1) * 16;
    uint32_t ap[8][4], an[8][4];
#pragma unroll
    for (int ks = 0; ks < 8; ++ks) {
        uint32_t rowoff = (uint32_t)(warp * 16 * PITCH + ks * 32) + aoff;
        ldm_x4(smp + rowoff, ap[ks]);
        ldm_x4(smn + rowoff, an[ks]);
    }

    int tg = lane >> 2, t4 = lane & 3;
    uint32_t bbase = sms + (uint32_t)(r7 * PITCH + ((lane >> 3) & 1) * 16);
    const float* Wrow = Wmat + (size_t)(warp * 16 + tg) * 256;
    float sp = 0.f, sn = 0.f;
#pragma unroll 2
    for (int nb = 0; nb < 32; ++nb) {
        int accp[4] = {0, 0, 0, 0};
        int accn[4] = {0, 0, 0, 0};
#pragma unroll
        for (int ks = 0; ks < 8; ++ks) {
            uint32_t b0, b1;
            ldm_x2(bbase + (uint32_t)(nb * 8 * PITCH + ks * 32), b0, b1);
            imma(accp, ap[ks], b0, b1);
            imma(accn, an[ks], b0, b1);
        }
        int cp = nb * 8 + 2 * t4;
        float2 wa = __ldg((const float2*)(Wrow + cp));
        float2 wb = __ldg((const float2*)(Wrow + 8 * 256 + cp));
        sp += i2f_small(accp[0]) * wa.x + i2f_small(accp[1]) * wa.y
            + i2f_small(accp[2]) * wb.x + i2f_small(accp[3]) * wb.y;
        sn += i2f_small(accn[0]) * wa.x + i2f_small(accn[1]) * wa.y
            + i2f_small(accn[2]) * wb.x + i2f_small(accn[3]) * wb.y;
    }

#pragma unroll
    for (int o = 16; o; o >>= 1) {
        sp += __shfl_xor_sync(0xffffffffu, sp, o);
        sn += __shfl_xor_sync(0xffffffffu, sn, o);
    }
    if (lane == 0) { s_red[warp] = sp; s_red[16 + warp] = sn; }
    __syncthreads();
    if (tid == 0) {
        float p = 0.f, n = 0.f;
#pragma unroll
        for (int w = 0; w < 16; ++w) { p += s_red[w]; n += s_red[16 + w]; }
        g_pos[t * BB + b] = p;
        g_neg[t * BB + b] = n;
    }
}

// ---------------- kernel 4: finalize scores + loss ----------------
__global__ void __launch_bounds__(384)
finalize_kernel(float* __restrict__ out) {
    __shared__ float s_red[TT * BB];
    __shared__ float s_lsn[TT];
    int i = threadIdx.x;            // 0..383 = t*32 + b
    int t = i >> 5;
    float mp = g_pos[i] * (1.0f / 65536.0f);
    float mn = g_neg[i] * (1.0f / 65536.0f);
    float lsp = logf(expf(mp) + 1e-4f);
    float sn = expf(mn) + 1e-4f;
    float s = sn;
#pragma unroll
    for (int o = 16; o; o >>= 1) s += __shfl_xor_sync(0xffffffffu, s, o);
    float lsn = logf(s);            // permutation-invariant sum over batch
    out[OUT_LSP_OFF + i] = lsp;
    if ((i & 31) == 0) s_lsn[t] = lsn;
    s_red[i] = lsn - lsp;
    __syncthreads();
    if (i < TT) out[OUT_LSN_OFF + i] = s_lsn[i];
    if (i == 0) {
        float acc = 0.f;
        for (int j = 0; j < TT * BB; ++j) acc += s_red[j];
        out[OUT_LOSS_OFF] = acc * (1.0f / (TT * BB));
    }
}

// ---------------- launch ----------------
extern "C" void kernel_launch(void* const* d_in, const int* in_sizes, int n_in,
                              void* d_out, int out_size) {
    const float* spk = (const float*)d_in[0];
    // d_in[1] = mem_rec (unused by reference outputs)
    const float* W = (const float*)d_in[2];
    const int* ridx = (const int*)d_in[3];
    float* out = (float*)d_out;

    cudaFuncSetAttribute(gemm_score_kernel,
                         cudaFuncAttributeMaxDynamicSharedMemorySize, DSMEM);

    prep_kernel<<<1, 32>>>(ridx);
    scan_copy_kernel<<<VEC_T / 256, 256>>>((const float4*)spk, (float4*)out);
    gemm_score_kernel<<<TT * BB, 512, DSMEM>>>(W);
    finalize_kernel<<<1, TT * BB>>>(out);
}

// round 12
// speedup vs baseline: 1.7740x; 1.6309x over previous
#include <cuda_runtime.h>
#include <cuda_bf16.h>
#include <cstdint>

// ---------------- problem constants ----------------
#define T_TOT 16
#define KLAG  4
#define TT    12          // T - K
#define BB    32
#define CC    256
#define HWN   256
#define ELEMS_T (BB*CC*HWN)       // 2097152 elements per timestep
#define VEC_T   (ELEMS_T/4)       // 524288 float4 per timestep

#define OUT_LOSS_OFF  33554432ull
#define OUT_LSP_OFF   33554433ull
#define OUT_LSN_OFF   33554817ull // 33554433 + 384

// ---------------- scratch (no allocs allowed) ----------------
__device__ unsigned char g_ctx[(size_t)TT * ELEMS_T];   // context bits {0,1}
__device__ unsigned char g_spk[(size_t)TT * ELEMS_T];   // spk bits, slot t = real t+4
__device__ float g_pos2[2 * TT * BB];                   // [mhalf][t*32+b]
__device__ float g_neg2[2 * TT * BB];
__device__ int   g_inv[BB];

// ---------------- helpers ----------------
__device__ __forceinline__ uint32_t smem_u32(const void* p) {
    uint32_t a;
    asm("{ .reg .u64 t; cvta.to.shared.u64 t, %1; cvt.u32.u64 %0, t; }"
        : "=r"(a) : "l"(p));
    return a;
}

__device__ __forceinline__ void ldm_x4(uint32_t addr, uint32_t* d) {
    asm volatile("ldmatrix.sync.aligned.m8n8.x4.shared.b16 {%0,%1,%2,%3}, [%4];"
        : "=r"(d[0]), "=r"(d[1]), "=r"(d[2]), "=r"(d[3]) : "r"(addr));
}
__device__ __forceinline__ void ldm_x2(uint32_t addr, uint32_t& b0, uint32_t& b1) {
    asm volatile("ldmatrix.sync.aligned.m8n8.x2.shared.b16 {%0,%1}, [%2];"
        : "=r"(b0), "=r"(b1) : "r"(addr));
}
// u8 x u8 -> s32 MMA (operands {0,1,128,129} x {0,1})
__device__ __forceinline__ void imma_u8(int* c, const uint32_t* a, uint32_t b0, uint32_t b1) {
    asm volatile("mma.sync.aligned.m16n8k32.row.col.s32.u8.u8.s32 "
        "{%0,%1,%2,%3}, {%4,%5,%6,%7}, {%8,%9}, {%0,%1,%2,%3};"
        : "+r"(c[0]), "+r"(c[1]), "+r"(c[2]), "+r"(c[3])
        : "r"(a[0]), "r"(a[1]), "r"(a[2]), "r"(a[3]), "r"(b0), "r"(b1));
}

// magic int->float for small non-negative ints (avoids I2F)
__device__ __forceinline__ float i2f_small(int v) {
    return __uint_as_float((uint32_t)v | 0x4B000000u) - 8388608.0f;
}

// ---------------- kernel 1: inverse permutation ----------------
__global__ void prep_kernel(const int* __restrict__ ridx) {
    int i = threadIdx.x;
    if (i < BB) g_inv[ridx[i]] = i;
}

// ---------------- kernel 2: copy + exact fp32 scan -> u8 scratch ----------------
// All 16 loads issued up front (MLP=16), then compute/store phase.
__global__ void __launch_bounds__(256)
scan_copy_kernel(const float4* __restrict__ in, float4* __restrict__ out) {
    int i = blockIdx.x * 256 + threadIdx.x;          // 0..524287, 4 hw-elements each
    float4 v[T_TOT];
#pragma unroll
    for (int t = 0; t < T_TOT; ++t) v[t] = in[(size_t)t * VEC_T + i];

    float4 m = make_float4(0.f, 0.f, 0.f, 0.f);
    uint32_t* ctxp = reinterpret_cast<uint32_t*>(g_ctx);
    uint32_t* spkp = reinterpret_cast<uint32_t*>(g_spk);
#pragma unroll
    for (int t = 0; t < T_TOT; ++t) {
        out[(size_t)t * VEC_T + i] = v[t];
        float rx = m.x > 1.0f ? 1.0f : 0.0f;
        float ry = m.y > 1.0f ? 1.0f : 0.0f;
        float rz = m.z > 1.0f ? 1.0f : 0.0f;
        float rw = m.w > 1.0f ? 1.0f : 0.0f;
        m.x = 0.5f * m.x + v[t].x - rx;
        m.y = 0.5f * m.y + v[t].y - ry;
        m.z = 0.5f * m.z + v[t].z - rz;
        m.w = 0.5f * m.w + v[t].w - rw;
        if (t < TT) {
            uint32_t u = (m.x > 1.0f ? 1u : 0u)
                       | (m.y > 1.0f ? 0x100u : 0u)
                       | (m.z > 1.0f ? 0x10000u : 0u)
                       | (m.w > 1.0f ? 0x1000000u : 0u);
            ctxp[(size_t)t * VEC_T + i] = u;
        }
        if (t >= KLAG) {
            uint32_t u = (v[t].x != 0.f ? 1u : 0u)
                       | (v[t].y != 0.f ? 0x100u : 0u)
                       | (v[t].z != 0.f ? 0x10000u : 0u)
                       | (v[t].w != 0.f ? 0x1000000u : 0u);
            spkp[(size_t)(t - KLAG) * VEC_T + i] = u;
        }
    }
}

// ---------------- kernel 3: combined-operand Gram via u8 IMMA ----------------
// CTA = (t, b, mhalf). comb = ctx_pos + 128*ctx_neg  (u8, one tensor pass for both).
// After each K=64 group (2 IMMAs): P = A & 127 (<=64, exact), N = A >> 7.
// 256 threads = 8 warps; warp w owns comb rows [16w, 16w+16) of the 128-row slab.

#define PITCH    272                       // 256 + 16 pad -> conflict-free ldmatrix
#define COMB_OFF 0
#define SPK_OFF  (128 * PITCH)             // 34816
#define DSMEM    (SPK_OFF + 256 * PITCH)   // 104448

__global__ void __launch_bounds__(256, 2)
gemm_score_kernel(const float* __restrict__ Wmat) {
    extern __shared__ __align__(16) char dsm[];
    __shared__ float s_red[16];
    int tid = threadIdx.x, warp = tid >> 5, lane = tid & 31;
    int bx = blockIdx.x;
    int mh = bx & 1;
    int tb = bx >> 1;                 // t*32 + b
    int t = tb >> 5, b = tb & 31;

    int binv = g_inv[b];
    // spk tile: full 256 rows
    const uint4* spk4 = (const uint4*)g_spk + (size_t)tb * 4096;
    for (int id = tid; id < 4096; id += 256) {
        int row = id >> 4, q = id & 15;
        *(uint4*)(dsm + SPK_OFF + row * PITCH + q * 16) = spk4[id];
    }
    // comb tile: 128 rows of this mhalf, pos | neg<<7
    const uint4* cpos = (const uint4*)g_ctx + (size_t)tb * 4096 + (size_t)mh * 2048;
    const uint4* cneg = (const uint4*)g_ctx + (size_t)(t * BB + binv) * 4096 + (size_t)mh * 2048;
    for (int id = tid; id < 2048; id += 256) {
        int row = id >> 4, q = id & 15;
        uint4 p = cpos[id];
        uint4 n = cneg[id];
        uint4 c;
        c.x = p.x | (n.x << 7);
        c.y = p.y | (n.y << 7);
        c.z = p.z | (n.z << 7);
        c.w = p.w | (n.w << 7);
        *(uint4*)(dsm + COMB_OFF + row * PITCH + q * 16) = c;
    }
    __syncthreads();

    uint32_t smc = smem_u32(dsm + COMB_OFF);
    uint32_t sms = smem_u32(dsm + SPK_OFF);

    // A fragments for this warp's 16 rows, full K=256 (8 k-steps of 32B)
    int sel = lane >> 3;
    int r7  = lane & 7;
    int aoff = ((sel & 1) * 8 + r7) * PITCH + (sel >> 1) * 16;
    uint32_t ac[8][4];
#pragma unroll
    for (int ks = 0; ks < 8; ++ks)
        ldm_x4(smc + (uint32_t)(warp * 16 * PITCH + ks * 32) + aoff, ac[ks]);

    int tg = lane >> 2, t4 = lane & 3;
    uint32_t bbase = sms + (uint32_t)(r7 * PITCH + ((lane >> 3) & 1) * 16);
    const float* Wrow = Wmat + (size_t)(mh * 128 + warp * 16 + tg) * 256;
    float sp = 0.f, sn = 0.f;
#pragma unroll 2
    for (int nb = 0; nb < 32; ++nb) {
        int accp[4] = {0, 0, 0, 0};
        int accn[4] = {0, 0, 0, 0};
#pragma unroll
        for (int g = 0; g < 4; ++g) {          // K groups of 64
            int a4[4] = {0, 0, 0, 0};
#pragma unroll
            for (int kk = 0; kk < 2; ++kk) {
                int ks = g * 2 + kk;
                uint32_t b0, b1;
                ldm_x2(bbase + (uint32_t)(nb * 8 * PITCH + ks * 32), b0, b1);
                imma_u8(a4, ac[ks], b0, b1);
            }
#pragma unroll
            for (int j = 0; j < 4; ++j) {
                accp[j] += a4[j] & 127;        // P <= 64, exact
                accn[j] += a4[j] >> 7;         // N
            }
        }
        int cp = nb * 8 + 2 * t4;
        float2 wa = __ldg((const float2*)(Wrow + cp));
        float2 wb = __ldg((const float2*)(Wrow + 8 * 256 + cp));
        sp += i2f_small(accp[0]) * wa.x + i2f_small(accp[1]) * wa.y
            + i2f_small(accp[2]) * wb.x + i2f_small(accp[3]) * wb.y;
        sn += i2f_small(accn[0]) * wa.x + i2f_small(accn[1]) * wa.y
            + i2f_small(accn[2]) * wb.x + i2f_small(accn[3]) * wb.y;
    }

#pragma unroll
    for (int o = 16; o; o >>= 1) {
        sp += __shfl_xor_sync(0xffffffffu, sp, o);
        sn += __shfl_xor_sync(0xffffffffu, sn, o);
    }
    if (lane == 0) { s_red[warp] = sp; s_red[8 + warp] = sn; }
    __syncthreads();
    if (tid == 0) {
        float p = 0.f, n = 0.f;
#pragma unroll
        for (int w = 0; w < 8; ++w) { p += s_red[w]; n += s_red[8 + w]; }
        g_pos2[mh * (TT * BB) + tb] = p;
        g_neg2[mh * (TT * BB) + tb] = n;
    }
}

// ---------------- kernel 4: finalize scores + loss ----------------
__global__ void __launch_bounds__(384)
finalize_kernel(float* __restrict__ out) {
    __shared__ float s_red[TT * BB];
    __shared__ float s_lsn[TT];
    int i = threadIdx.x;            // 0..383 = t*32 + b
    int t = i >> 5;
    float mp = (g_pos2[i] + g_pos2[TT * BB + i]) * (1.0f / 65536.0f);
    float mn = (g_neg2[i] + g_neg2[TT * BB + i]) * (1.0f / 65536.0f);
    float lsp = logf(expf(mp) + 1e-4f);
    float sn = expf(mn) + 1e-4f;
    float s = sn;
#pragma unroll
    for (int o = 16; o; o >>= 1) s += __shfl_xor_sync(0xffffffffu, s, o);
    float lsn = logf(s);            // permutation-invariant sum over batch
    out[OUT_LSP_OFF + i] = lsp;
    if ((i & 31) == 0) s_lsn[t] = lsn;
    s_red[i] = lsn - lsp;
    __syncthreads();
    if (i < TT) out[OUT_LSN_OFF + i] = s_lsn[i];
    if (i == 0) {
        float acc = 0.f;
        for (int j = 0; j < TT * BB; ++j) acc += s_red[j];
        out[OUT_LOSS_OFF] = acc * (1.0f / (TT * BB));
    }
}

// ---------------- launch ----------------
extern "C" void kernel_launch(void* const* d_in, const int* in_sizes, int n_in,
                              void* d_out, int out_size) {
    const float* spk = (const float*)d_in[0];
    // d_in[1] = mem_rec (unused by reference outputs)
    const float* W = (const float*)d_in[2];
    const int* ridx = (const int*)d_in[3];
    float* out = (float*)d_out;

    cudaFuncSetAttribute(gemm_score_kernel,
                         cudaFuncAttributeMaxDynamicSharedMemorySize, DSMEM);

    prep_kernel<<<1, 32>>>(ridx);
    scan_copy_kernel<<<VEC_T / 256, 256>>>((const float4*)spk, (float4*)out);
    gemm_score_kernel<<<TT * BB * 2, 256, DSMEM>>>(W);
    finalize_kernel<<<1, TT * BB>>>(out);
}

// round 16
// speedup vs baseline: 1.8090x; 1.0197x over previous
#include <cuda_runtime.h>
#include <cuda_bf16.h>
#include <cstdint>

// ---------------- problem constants ----------------
#define T_TOT 16
#define KLAG  4
#define TT    12          // T - K
#define BB    32
#define CC    256
#define HWN   256
#define ELEMS_T (BB*CC*HWN)       // 2097152 elements per timestep
#define VEC_T   (ELEMS_T/4)       // 524288 float4 per timestep

#define OUT_LOSS_OFF  33554432ull
#define OUT_LSP_OFF   33554433ull
#define OUT_LSN_OFF   33554817ull // 33554433 + 384

#define GRID_GEMM (TT * BB * 2)   // 768

// ---------------- scratch (no allocs allowed) ----------------
__device__ unsigned char g_ctx[(size_t)TT * ELEMS_T];   // context bits {0,1}
__device__ unsigned char g_spk[(size_t)TT * ELEMS_T];   // spk bits, slot t = real t+4
__device__ float g_pos2[2 * TT * BB];                   // [mhalf][t*32+b]
__device__ float g_neg2[2 * TT * BB];
__device__ int   g_inv[BB];
__device__ unsigned int g_done;                         // ticket for last-CTA finalize

// ---------------- helpers ----------------
__device__ __forceinline__ uint32_t smem_u32(const void* p) {
    uint32_t a;
    asm("{ .reg .u64 t; cvta.to.shared.u64 t, %1; cvt.u32.u64 %0, t; }"
        : "=r"(a) : "l"(p));
    return a;
}

__device__ __forceinline__ void ldm_x4(uint32_t addr, uint32_t* d) {
    asm volatile("ldmatrix.sync.aligned.m8n8.x4.shared.b16 {%0,%1,%2,%3}, [%4];"
        : "=r"(d[0]), "=r"(d[1]), "=r"(d[2]), "=r"(d[3]) : "r"(addr));
}
// u8 x u8 -> s32 MMA (operands {0,1,128,129} x {0,1})
__device__ __forceinline__ void imma_u8(int* c, const uint32_t* a, uint32_t b0, uint32_t b1) {
    asm volatile("mma.sync.aligned.m16n8k32.row.col.s32.u8.u8.s32 "
        "{%0,%1,%2,%3}, {%4,%5,%6,%7}, {%8,%9}, {%0,%1,%2,%3};"
        : "+r"(c[0]), "+r"(c[1]), "+r"(c[2]), "+r"(c[3])
        : "r"(a[0]), "r"(a[1]), "r"(a[2]), "r"(a[3]), "r"(b0), "r"(b1));
}

// magic int->float for small non-negative ints (avoids I2F)
__device__ __forceinline__ float i2f_small(int v) {
    return __uint_as_float((uint32_t)v | 0x4B000000u) - 8388608.0f;
}

// ---------------- kernel 1: copy + exact fp32 scan -> u8 scratch (+ prep) -------
// All 16 loads issued up front (MLP=16). out stored streaming (evict-first) so the
// 50 MB ctx/spk scratch stays L2-resident for the gemm kernel.
__global__ void __launch_bounds__(256)
scan_copy_kernel(const float4* __restrict__ in, float4* __restrict__ out,
                 const int* __restrict__ ridx) {
    if (blockIdx.x == 0 && threadIdx.x < BB) g_inv[ridx[threadIdx.x]] = threadIdx.x;

    int i = blockIdx.x * 256 + threadIdx.x;          // 0..524287, 4 hw-elements each
    float4 v[T_TOT];
#pragma unroll
    for (int t = 0; t < T_TOT; ++t) v[t] = __ldcs(in + (size_t)t * VEC_T + i);

    float4 m = make_float4(0.f, 0.f, 0.f, 0.f);
    uint32_t* ctxp = reinterpret_cast<uint32_t*>(g_ctx);
    uint32_t* spkp = reinterpret_cast<uint32_t*>(g_spk);
#pragma unroll
    for (int t = 0; t < T_TOT; ++t) {
        __stcs(out + (size_t)t * VEC_T + i, v[t]);
        float rx = m.x > 1.0f ? 1.0f : 0.0f;
        float ry = m.y > 1.0f ? 1.0f : 0.0f;
        float rz = m.z > 1.0f ? 1.0f : 0.0f;
        float rw = m.w > 1.0f ? 1.0f : 0.0f;
        m.x = 0.5f * m.x + v[t].x - rx;
        m.y = 0.5f * m.y + v[t].y - ry;
        m.z = 0.5f * m.z + v[t].z - rz;
        m.w = 0.5f * m.w + v[t].w - rw;
        if (t < TT) {
            uint32_t u = (m.x > 1.0f ? 1u : 0u)
                       | (m.y > 1.0f ? 0x100u : 0u)
                       | (m.z > 1.0f ? 0x10000u : 0u)
                       | (m.w > 1.0f ? 0x1000000u : 0u);
            ctxp[(size_t)t * VEC_T + i] = u;
        }
        if (t >= KLAG) {
            uint32_t u = (v[t].x != 0.f ? 1u : 0u)
                       | (v[t].y != 0.f ? 0x100u : 0u)
                       | (v[t].z != 0.f ? 0x10000u : 0u)
                       | (v[t].w != 0.f ? 0x1000000u : 0u);
            spkp[(size_t)(t - KLAG) * VEC_T + i] = u;
        }
    }
}

// ---------------- kernel 2: combined-operand Gram via u8 IMMA (+ finalize) -------
// CTA = (t, b, mhalf). comb = ctx_pos + 128*ctx_neg  (one tensor pass for both).
// Decode after each <=3-IMMA group (P <= 96 < 128): P = A & 127, N = A >> 7, exact.
// B fragments via ldmatrix.x4 spanning TWO n-blocks (nb-pair per iteration).
// Last CTA (atomic ticket) computes the loss/log-scores in-kernel.

#define PITCH    272                       // 256 + 16 pad -> conflict-free ldmatrix
#define COMB_OFF 0
#define SPK_OFF  (128 * PITCH)             // 34816
#define DSMEM    (SPK_OFF + 256 * PITCH)   // 104448

__global__ void __launch_bounds__(256, 2)
gemm_score_kernel(const float* __restrict__ Wmat, float* __restrict__ out) {
    extern __shared__ __align__(16) char dsm[];
    __shared__ float s_red[16];
    __shared__ int   s_last;
    __shared__ float s_fin[TT * BB];
    int tid = threadIdx.x, warp = tid >> 5, lane = tid & 31;
    int bx = blockIdx.x;
    int mh = bx & 1;
    int tb = bx >> 1;                 // t*32 + b
    int t = tb >> 5, b = tb & 31;

    int binv = g_inv[b];
    // spk tile: full 256 rows
    const uint4* spk4 = (const uint4*)g_spk + (size_t)tb * 4096;
    for (int id = tid; id < 4096; id += 256) {
        int row = id >> 4, q = id & 15;
        *(uint4*)(dsm + SPK_OFF + row * PITCH + q * 16) = spk4[id];
    }
    // comb tile: 128 rows of this mhalf, pos | neg<<7
    const uint4* cpos = (const uint4*)g_ctx + (size_t)tb * 4096 + (size_t)mh * 2048;
    const uint4* cneg = (const uint4*)g_ctx + (size_t)(t * BB + binv) * 4096 + (size_t)mh * 2048;
    for (int id = tid; id < 2048; id += 256) {
        int row = id >> 4, q = id & 15;
        uint4 p = cpos[id];
        uint4 n = cneg[id];
        uint4 c;
        c.x = p.x | (n.x << 7);
        c.y = p.y | (n.y << 7);
        c.z = p.z | (n.z << 7);
        c.w = p.w | (n.w << 7);
        *(uint4*)(dsm + COMB_OFF + row * PITCH + q * 16) = c;
    }
    __syncthreads();

    uint32_t smc = smem_u32(dsm + COMB_OFF);
    uint32_t sms = smem_u32(dsm + SPK_OFF);

    // A fragments for this warp's 16 rows, full K=256 (8 k-steps of 32B)
    int sel = lane >> 3;
    int r7  = lane & 7;
    int aoff = ((sel & 1) * 8 + r7) * PITCH + (sel >> 1) * 16;
    uint32_t ac[8][4];
#pragma unroll
    for (int ks = 0; ks < 8; ++ks)
        ldm_x4(smc + (uint32_t)(warp * 16 * PITCH + ks * 32) + aoff, ac[ks]);

    // B frag base: matrices 0/1 = nb-even (k lo/hi), 2/3 = nb-odd rows (+8)
    int tg = lane >> 2, t4 = lane & 3;
    uint32_t bbase = sms + (uint32_t)(((lane >> 4) * 8 + r7) * PITCH
                                     + ((lane >> 3) & 1) * 16);
    const float* Wrow = Wmat + (size_t)(mh * 128 + warp * 16 + tg) * 256;
    float sp = 0.f, sn = 0.f;

    const int gsz[3] = {3, 3, 2};        // K groups of 96,96,64 (P<=96<128: exact)
#pragma unroll 2
    for (int nbp = 0; nbp < 16; ++nbp) {
        int accp[2][4] = {{0,0,0,0},{0,0,0,0}};
        int accn[2][4] = {{0,0,0,0},{0,0,0,0}};
        int ks = 0;
#pragma unroll
        for (int g = 0; g < 3; ++g) {
            int a4[2][4] = {{0,0,0,0},{0,0,0,0}};
#pragma unroll
            for (int kk = 0; kk < 3; ++kk) {
                if (kk < gsz[g]) {
                    uint32_t d[4];
                    ldm_x4(bbase + (uint32_t)(nbp * 16 * PITCH + ks * 32), d);
                    imma_u8(a4[0], ac[ks], d[0], d[1]);
                    imma_u8(a4[1], ac[ks], d[2], d[3]);
                    ++ks;
                }
            }
#pragma unroll
            for (int h = 0; h < 2; ++h)
#pragma unroll
                for (int j = 0; j < 4; ++j) {
                    accp[h][j] += a4[h][j] & 127;
                    accn[h][j] += a4[h][j] >> 7;
                }
        }
#pragma unroll
        for (int h = 0; h < 2; ++h) {
            int cp = (nbp * 2 + h) * 8 + 2 * t4;
            float2 wa = __ldg((const float2*)(Wrow + cp));
            float2 wb = __ldg((const float2*)(Wrow + 8 * 256 + cp));
            sp += i2f_small(accp[h][0]) * wa.x + i2f_small(accp[h][1]) * wa.y
                + i2f_small(accp[h][2]) * wb.x + i2f_small(accp[h][3]) * wb.y;
            sn += i2f_small(accn[h][0]) * wa.x + i2f_small(accn[h][1]) * wa.y
                + i2f_small(accn[h][2]) * wb.x + i2f_small(accn[h][3]) * wb.y;
        }
    }

#pragma unroll
    for (int o = 16; o; o >>= 1) {
        sp += __shfl_xor_sync(0xffffffffu, sp, o);
        sn += __shfl_xor_sync(0xffffffffu, sn, o);
    }
    if (lane == 0) { s_red[warp] = sp; s_red[8 + warp] = sn; }
    __syncthreads();
    if (tid == 0) {
        float p = 0.f, n = 0.f;
#pragma unroll
        for (int w = 0; w < 8; ++w) { p += s_red[w]; n += s_red[8 + w]; }
        g_pos2[mh * (TT * BB) + tb] = p;
        g_neg2[mh * (TT * BB) + tb] = n;
        __threadfence();
        unsigned int v = atomicAdd(&g_done, 1u);
        s_last = (v == GRID_GEMM - 1) ? 1 : 0;
    }
    __syncthreads();

    // ---- last CTA: finalize scores + loss ----
    if (s_last) {
        for (int i = tid; i < TT * BB; i += 256) {
            float mp = (g_pos2[i] + g_pos2[TT * BB + i]) * (1.0f / 65536.0f);
            float mn = (g_neg2[i] + g_neg2[TT * BB + i]) * (1.0f / 65536.0f);
            float lsp = logf(expf(mp) + 1e-4f);
            float s = expf(mn) + 1e-4f;
#pragma unroll
            for (int o = 16; o; o >>= 1) s += __shfl_xor_sync(0xffffffffu, s, o);
            float lsn = logf(s);            // permutation-invariant sum over batch
            out[OUT_LSP_OFF + i] = lsp;
            if ((i & 31) == 0) out[OUT_LSN_OFF + (i >> 5)] = lsn;
            s_fin[i] = lsn - lsp;
        }
        __syncthreads();
        if (tid == 0) {
            float acc = 0.f;
            for (int j = 0; j < TT * BB; ++j) acc += s_fin[j];
            out[OUT_LOSS_OFF] = acc * (1.0f / (TT * BB));
            g_done = 0;                     // reset ticket for graph replay
        }
    }
}

// ---------------- launch ----------------
extern "C" void kernel_launch(void* const* d_in, const int* in_sizes, int n_in,
                              void* d_out, int out_size) {
    const float* spk = (const float*)d_in[0];
    // d_in[1] = mem_rec (unused by reference outputs)
    const float* W = (const float*)d_in[2];
    const int* ridx = (const int*)d_in[3];
    float* out = (float*)d_out;

    cudaFuncSetAttribute(gemm_score_kernel,
                         cudaFuncAttributeMaxDynamicSharedMemorySize, DSMEM);

    scan_copy_kernel<<<VEC_T / 256, 256>>>((const float4*)spk, (float4*)out, ridx);
    gemm_score_kernel<<<GRID_GEMM, 256, DSMEM>>>(W, out);
}

// round 17
// speedup vs baseline: 1.9107x; 1.0562x over previous
#include <cuda_runtime.h>
#include <cuda_bf16.h>
#include <cstdint>

// ---------------- problem constants ----------------
#define T_TOT 16
#define KLAG  4
#define TT    12          // T - K
#define BB    32
#define CC    256
#define HWN   256
#define ELEMS_T (BB*CC*HWN)       // 2097152 elements per timestep
#define VEC_T   (ELEMS_T/4)       // 524288 float4 per timestep

#define OUT_LOSS_OFF  33554432ull
#define OUT_LSP_OFF   33554433ull
#define OUT_LSN_OFF   33554817ull // 33554433 + 384

#define GRID_GEMM (TT * BB * 4)   // 1536: (t, b, mhalf, nhalf)

// ---------------- scratch (no allocs allowed) ----------------
__device__ unsigned char g_ctx[(size_t)TT * ELEMS_T];   // context bits {0,1}
__device__ unsigned char g_spk[(size_t)TT * ELEMS_T];   // spk bits, slot t = real t+4
__device__ float g_posq[4][TT * BB];                    // [quad][t*32+b]
__device__ float g_negq[4][TT * BB];
__device__ int   g_inv[BB];
__device__ unsigned int g_done;                         // ticket for last-CTA finalize

// ---------------- helpers ----------------
__device__ __forceinline__ uint32_t smem_u32(const void* p) {
    uint32_t a;
    asm("{ .reg .u64 t; cvta.to.shared.u64 t, %1; cvt.u32.u64 %0, t; }"
        : "=r"(a) : "l"(p));
    return a;
}

__device__ __forceinline__ void ldm_x4(uint32_t addr, uint32_t* d) {
    asm volatile("ldmatrix.sync.aligned.m8n8.x4.shared.b16 {%0,%1,%2,%3}, [%4];"
        : "=r"(d[0]), "=r"(d[1]), "=r"(d[2]), "=r"(d[3]) : "r"(addr));
}
// u8 x u8 -> s32 MMA (operands {0,1,128,129} x {0,1})
__device__ __forceinline__ void imma_u8(int* c, const uint32_t* a, uint32_t b0, uint32_t b1) {
    asm volatile("mma.sync.aligned.m16n8k32.row.col.s32.u8.u8.s32 "
        "{%0,%1,%2,%3}, {%4,%5,%6,%7}, {%8,%9}, {%0,%1,%2,%3};"
        : "+r"(c[0]), "+r"(c[1]), "+r"(c[2]), "+r"(c[3])
        : "r"(a[0]), "r"(a[1]), "r"(a[2]), "r"(a[3]), "r"(b0), "r"(b1));
}

// magic int->float for small non-negative ints (avoids I2F)
__device__ __forceinline__ float i2f_small(int v) {
    return __uint_as_float((uint32_t)v | 0x4B000000u) - 8388608.0f;
}

// ---------------- kernel 1: copy + exact fp32 scan -> u8 scratch (+ prep) -------
// All 16 loads issued up front (MLP=16). out stored streaming (evict-first) so the
// 50 MB ctx/spk scratch stays L2-resident for the gemm kernel.
__global__ void __launch_bounds__(256)
scan_copy_kernel(const float4* __restrict__ in, float4* __restrict__ out,
                 const int* __restrict__ ridx) {
    if (blockIdx.x == 0 && threadIdx.x < BB) g_inv[ridx[threadIdx.x]] = threadIdx.x;

    int i = blockIdx.x * 256 + threadIdx.x;          // 0..524287, 4 hw-elements each
    float4 v[T_TOT];
#pragma unroll
    for (int t = 0; t < T_TOT; ++t) v[t] = __ldcs(in + (size_t)t * VEC_T + i);

    float4 m = make_float4(0.f, 0.f, 0.f, 0.f);
    uint32_t* ctxp = reinterpret_cast<uint32_t*>(g_ctx);
    uint32_t* spkp = reinterpret_cast<uint32_t*>(g_spk);
#pragma unroll
    for (int t = 0; t < T_TOT; ++t) {
        __stcs(out + (size_t)t * VEC_T + i, v[t]);
        float rx = m.x > 1.0f ? 1.0f : 0.0f;
        float ry = m.y > 1.0f ? 1.0f : 0.0f;
        float rz = m.z > 1.0f ? 1.0f : 0.0f;
        float rw = m.w > 1.0f ? 1.0f : 0.0f;
        m.x = 0.5f * m.x + v[t].x - rx;
        m.y = 0.5f * m.y + v[t].y - ry;
        m.z = 0.5f * m.z + v[t].z - rz;
        m.w = 0.5f * m.w + v[t].w - rw;
        if (t < TT) {
            uint32_t u = (m.x > 1.0f ? 1u : 0u)
                       | (m.y > 1.0f ? 0x100u : 0u)
                       | (m.z > 1.0f ? 0x10000u : 0u)
                       | (m.w > 1.0f ? 0x1000000u : 0u);
            ctxp[(size_t)t * VEC_T + i] = u;
        }
        if (t >= KLAG) {
            uint32_t u = (v[t].x != 0.f ? 1u : 0u)
                       | (v[t].y != 0.f ? 0x100u : 0u)
                       | (v[t].z != 0.f ? 0x10000u : 0u)
                       | (v[t].w != 0.f ? 0x1000000u : 0u);
            spkp[(size_t)(t - KLAG) * VEC_T + i] = u;
        }
    }
}

// ---------------- kernel 2: combined-operand Gram via u8 IMMA (+ finalize) -------
// CTA = (t, b, mhalf, nhalf): comb = ctx_pos + 128*ctx_neg (128 M-rows of mhalf),
// spk tile = 128 N-rows of nhalf. Decode after <=3-IMMA groups (P<=96<128, exact).
// K split in halves so only 4 A-fragments are resident (regs), N split so smem is
// 69.6 KB -> 3 CTAs/SM (24 warps). Last CTA (atomic ticket) finalizes the loss.

#define PITCH    272                       // 256 + 16 pad -> conflict-free ldmatrix
#define COMB_OFF 0
#define SPK_OFF  (128 * PITCH)             // 34816
#define DSMEM    (256 * PITCH)             // 69632

__global__ void __launch_bounds__(256, 3)
gemm_score_kernel(const float* __restrict__ Wmat, float* __restrict__ out) {
    extern __shared__ __align__(16) char dsm[];
    __shared__ float s_red[16];
    __shared__ int   s_last;
    __shared__ float s_fin[TT * BB];
    int tid = threadIdx.x, warp = tid >> 5, lane = tid & 31;
    int bx = blockIdx.x;
    int quad = bx & 3;                // mh + 2*nh
    int mh = bx & 1;
    int nh = (bx >> 1) & 1;
    int tb = bx >> 2;                 // t*32 + b
    int t = tb >> 5, b = tb & 31;

    int binv = g_inv[b];
    // spk tile: 128 rows of this nhalf
    const uint4* spk4 = (const uint4*)g_spk + (size_t)tb * 4096 + (size_t)nh * 2048;
    for (int id = tid; id < 2048; id += 256) {
        int row = id >> 4, q = id & 15;
        *(uint4*)(dsm + SPK_OFF + row * PITCH + q * 16) = spk4[id];
    }
    // comb tile: 128 rows of this mhalf, pos | neg<<7
    const uint4* cpos = (const uint4*)g_ctx + (size_t)tb * 4096 + (size_t)mh * 2048;
    const uint4* cneg = (const uint4*)g_ctx + (size_t)(t * BB + binv) * 4096 + (size_t)mh * 2048;
    for (int id = tid; id < 2048; id += 256) {
        int row = id >> 4, q = id & 15;
        uint4 p = cpos[id];
        uint4 n = cneg[id];
        uint4 c;
        c.x = p.x | (n.x << 7);
        c.y = p.y | (n.y << 7);
        c.z = p.z | (n.z << 7);
        c.w = p.w | (n.w << 7);
        *(uint4*)(dsm + COMB_OFF + row * PITCH + q * 16) = c;
    }
    __syncthreads();

    uint32_t smc = smem_u32(dsm + COMB_OFF);
    uint32_t sms = smem_u32(dsm + SPK_OFF);

    int sel = lane >> 3;
    int r7  = lane & 7;
    int aoff = ((sel & 1) * 8 + r7) * PITCH + (sel >> 1) * 16;
    // B frag base: matrices 0/1 = nb-even (k lo/hi), 2/3 = nb-odd rows (+8)
    int tg = lane >> 2, t4 = lane & 3;
    uint32_t bbase = sms + (uint32_t)(((lane >> 4) * 8 + r7) * PITCH
                                     + ((lane >> 3) & 1) * 16);
    const float* Wrow = Wmat + (size_t)(mh * 128 + warp * 16 + tg) * 256 + nh * 128;
    float sp = 0.f, sn = 0.f;

    for (int h2 = 0; h2 < 2; ++h2) {          // K halves (4 k-steps each)
        uint32_t ac[4][4];
#pragma unroll
        for (int kk = 0; kk < 4; ++kk)
            ldm_x4(smc + (uint32_t)(warp * 16 * PITCH + (h2 * 4 + kk) * 32) + aoff,
                   ac[kk]);
#pragma unroll 2
        for (int nbp = 0; nbp < 8; ++nbp) {   // pairs of n-blocks (16 rows)
            int accp[2][4] = {{0,0,0,0},{0,0,0,0}};
            int accn[2][4] = {{0,0,0,0},{0,0,0,0}};
            // group 0: 3 chained IMMAs (P <= 96 < 128, exact)
            {
                int a4[2][4] = {{0,0,0,0},{0,0,0,0}};
#pragma unroll
                for (int kk = 0; kk < 3; ++kk) {
                    uint32_t d[4];
                    ldm_x4(bbase + (uint32_t)(nbp * 16 * PITCH + (h2 * 4 + kk) * 32), d);
                    imma_u8(a4[0], ac[kk], d[0], d[1]);
                    imma_u8(a4[1], ac[kk], d[2], d[3]);
                }
#pragma unroll
                for (int h = 0; h < 2; ++h)
#pragma unroll
                    for (int j = 0; j < 4; ++j) {
                        accp[h][j] += a4[h][j] & 127;
                        accn[h][j] += a4[h][j] >> 7;
                    }
            }
            // group 1: 1 IMMA
            {
                int a4[2][4] = {{0,0,0,0},{0,0,0,0}};
                uint32_t d[4];
                ldm_x4(bbase + (uint32_t)(nbp * 16 * PITCH + (h2 * 4 + 3) * 32), d);
                imma_u8(a4[0], ac[3], d[0], d[1]);
                imma_u8(a4[1], ac[3], d[2], d[3]);
#pragma unroll
                for (int h = 0; h < 2; ++h)
#pragma unroll
                    for (int j = 0; j < 4; ++j) {
                        accp[h][j] += a4[h][j] & 127;
                        accn[h][j] += a4[h][j] >> 7;
                    }
            }
            // W contraction for this (nbp, khalf)
#pragma unroll
            for (int h = 0; h < 2; ++h) {
                int cp = (nbp * 2 + h) * 8 + 2 * t4;
                float2 wa = __ldg((const float2*)(Wrow + cp));
                float2 wb = __ldg((const float2*)(Wrow + 8 * 256 + cp));
                sp += i2f_small(accp[h][0]) * wa.x + i2f_small(accp[h][1]) * wa.y
                    + i2f_small(accp[h][2]) * wb.x + i2f_small(accp[h][3]) * wb.y;
                sn += i2f_small(accn[h][0]) * wa.x + i2f_small(accn[h][1]) * wa.y
                    + i2f_small(accn[h][2]) * wb.x + i2f_small(accn[h][3]) * wb.y;
            }
        }
    }

#pragma unroll
    for (int o = 16; o; o >>= 1) {
        sp += __shfl_xor_sync(0xffffffffu, sp, o);
        sn += __shfl_xor_sync(0xffffffffu, sn, o);
    }
    if (lane == 0) { s_red[warp] = sp; s_red[8 + warp] = sn; }
    __syncthreads();
    if (tid == 0) {
        float p = 0.f, n = 0.f;
#pragma unroll
        for (int w = 0; w < 8; ++w) { p += s_red[w]; n += s_red[8 + w]; }
        g_posq[quad][tb] = p;
        g_negq[quad][tb] = n;
        __threadfence();
        unsigned int v = atomicAdd(&g_done, 1u);
        s_last = (v == GRID_GEMM - 1) ? 1 : 0;
    }
    __syncthreads();

    // ---- last CTA: finalize scores + loss ----
    if (s_last) {
        for (int i = tid; i < TT * BB; i += 256) {
            float mp = (g_posq[0][i] + g_posq[1][i] + g_posq[2][i] + g_posq[3][i])
                       * (1.0f / 65536.0f);
            float mn = (g_negq[0][i] + g_negq[1][i] + g_negq[2][i] + g_negq[3][i])
                       * (1.0f / 65536.0f);
            float lsp = logf(expf(mp) + 1e-4f);
            float s = expf(mn) + 1e-4f;
#pragma unroll
            for (int o = 16; o; o >>= 1) s += __shfl_xor_sync(0xffffffffu, s, o);
            float lsn = logf(s);            // permutation-invariant sum over batch
            out[OUT_LSP_OFF + i] = lsp;
            if ((i & 31) == 0) out[OUT_LSN_OFF + (i >> 5)] = lsn;
            s_fin[i] = lsn - lsp;
        }
        __syncthreads();
        if (tid == 0) {
            float acc = 0.f;
            for (int j = 0; j < TT * BB; ++j) acc += s_fin[j];
            out[OUT_LOSS_OFF] = acc * (1.0f / (TT * BB));
            g_done = 0;                     // reset ticket for graph replay
        }
    }
}

// ---------------- launch ----------------
extern "C" void kernel_launch(void* const* d_in, const int* in_sizes, int n_in,
                              void* d_out, int out_size) {
    const float* spk = (const float*)d_in[0];
    // d_in[1] = mem_rec (unused by reference outputs)
    const float* W = (const float*)d_in[2];
    const int* ridx = (const int*)d_in[3];
    float* out = (float*)d_out;

    cudaFuncSetAttribute(gemm_score_kernel,
                         cudaFuncAttributeMaxDynamicSharedMemorySize, DSMEM);

    scan_copy_kernel<<<VEC_T / 256, 256>>>((const float4*)spk, (float4*)out, ridx);
    gemm_score_kernel<<<GRID_GEMM, 256, DSMEM>>>(W, out);
}